// round 1
// baseline (speedup 1.0000x reference)
#include <cuda_runtime.h>
#include <cstdint>

// Problem constants (fixed by the dataset)
#define N_NODES 100000
#define N_EDGES 3200000
#define DIM     64
#define EPS     1e-16f

// ---------------- device scratch (static globals: allocation-free) ----------
__device__ int   g_in_max[N_NODES];    // ordered-int encoded max of incoming logits
__device__ int   g_out_max[N_NODES];   // ordered-int encoded max of outgoing logits
__device__ float g_in_sum[N_NODES];    // sum exp(l - m) over incoming edges
__device__ float g_out_sum[N_NODES];   // sum exp(l - m) over outgoing edges
__device__ float g_norm[N_EDGES];      // sqrt(softmax_in * softmax_out) per edge
__device__ float g_bufA[(size_t)N_NODES * DIM];
__device__ float g_bufB[(size_t)N_NODES * DIM];

// ---------------- helpers ----------------------------------------------------
// Order-preserving float<->int encoding so atomicMax(int) implements float max.
__device__ __forceinline__ int enc_f(float f) {
    int i = __float_as_int(f);
    return (i >= 0) ? i : (i ^ 0x7FFFFFFF);
}
__device__ __forceinline__ float dec_f(int i) {
    return __int_as_float((i >= 0) ? i : (i ^ 0x7FFFFFFF));
}

// ---------------- kernels ----------------------------------------------------
__global__ void k_init_stats() {
    int i = blockIdx.x * blockDim.x + threadIdx.x;
    if (i < N_NODES) {
        g_in_max[i]  = (int)0x80000000;   // < any encoded finite float
        g_out_max[i] = (int)0x80000000;
        g_in_sum[i]  = 0.0f;
        g_out_sum[i] = 0.0f;
    }
}

__global__ void k_edge_max(const int* __restrict__ ei, const float* __restrict__ attr) {
    int e = blockIdx.x * blockDim.x + threadIdx.x;
    if (e >= N_EDGES) return;
    int f = ei[e];
    int t = ei[e + N_EDGES];
    int v = enc_f(attr[e]);  // s_temp = 1.0 -> logits == attr
    atomicMax(&g_in_max[t], v);
    atomicMax(&g_out_max[f], v);
}

__global__ void k_edge_expsum(const int* __restrict__ ei, const float* __restrict__ attr) {
    int e = blockIdx.x * blockDim.x + threadIdx.x;
    if (e >= N_EDGES) return;
    int f = ei[e];
    int t = ei[e + N_EDGES];
    float l = attr[e];
    float m_in  = dec_f(g_in_max[t]);
    float m_out = dec_f(g_out_max[f]);
    atomicAdd(&g_in_sum[t],  __expf(l - m_in));
    atomicAdd(&g_out_sum[f], __expf(l - m_out));
}

__global__ void k_edge_norm(const int* __restrict__ ei, const float* __restrict__ attr) {
    int e = blockIdx.x * blockDim.x + threadIdx.x;
    if (e >= N_EDGES) return;
    int f = ei[e];
    int t = ei[e + N_EDGES];
    float l = attr[e];
    float m_in  = dec_f(g_in_max[t]);
    float m_out = dec_f(g_out_max[f]);
    float s_in  = g_in_sum[t]  + EPS;
    float s_out = g_out_sum[f] + EPS;
    // sqrt( e_in/s_in * e_out/s_out ) = exp(l - (m_in+m_out)/2) * rsqrt(s_in*s_out)
    g_norm[e] = __expf(l - 0.5f * (m_in + m_out)) * rsqrtf(s_in * s_out);
}

// 16 threads per edge; each thread handles one float4 (4 of 64 dims).
__global__ void k_propagate(const float* __restrict__ src, float* __restrict__ dst,
                            const int* __restrict__ ei) {
    int gid = blockIdx.x * blockDim.x + threadIdx.x;
    int e   = gid >> 4;
    int sub = gid & 15;
    if (e >= N_EDGES) return;
    int f = ei[e];
    int t = ei[e + N_EDGES];
    float w = g_norm[e];
    const float4* srow = reinterpret_cast<const float4*>(src + (size_t)f * DIM);
    float4 v = srow[sub];
    v.x *= w; v.y *= w; v.z *= w; v.w *= w;
    float* d = dst + (size_t)t * DIM + sub * 4;
    asm volatile("red.global.add.v4.f32 [%0], {%1, %2, %3, %4};"
                 :: "l"(d), "f"(v.x), "f"(v.y), "f"(v.z), "f"(v.w)
                 : "memory");
}

__global__ void k_accumulate(float* __restrict__ acc, const float* __restrict__ x) {
    int i = blockIdx.x * blockDim.x + threadIdx.x;
    if (i < N_NODES * DIM) acc[i] += x[i];
}

__global__ void k_accumulate_scale(float* __restrict__ acc, const float* __restrict__ x,
                                   float scale) {
    int i = blockIdx.x * blockDim.x + threadIdx.x;
    if (i < N_NODES * DIM) acc[i] = (acc[i] + x[i]) * scale;
}

// ---------------- launch ------------------------------------------------------
extern "C" void kernel_launch(void* const* d_in, const int* in_sizes, int n_in,
                              void* d_out, int out_size) {
    const float* emb  = (const float*)d_in[0];   // [N_NODES, 64]
    const int*   ei   = (const int*)d_in[1];     // [2, N_EDGES]
    const float* attr = (const float*)d_in[2];   // [N_EDGES]
    float* out = (float*)d_out;                  // [2 * N_NODES * 64]
    float* acc = out + (size_t)N_NODES * DIM;    // second tuple element

    float *bufA, *bufB;
    cudaGetSymbolAddress((void**)&bufA, g_bufA);
    cudaGetSymbolAddress((void**)&bufB, g_bufB);

    const size_t node_bytes = (size_t)N_NODES * DIM * sizeof(float);
    const int TB = 256;
    const int grid_nodes = (N_NODES + TB - 1) / TB;
    const int grid_edges = (N_EDGES + TB - 1) / TB;
    const int grid_prop  = (int)(((size_t)N_EDGES * 16 + TB - 1) / TB);
    const int grid_nd    = (N_NODES * DIM + TB - 1) / TB;

    // Softmax statistics
    k_init_stats<<<grid_nodes, TB>>>();
    k_edge_max<<<grid_edges, TB>>>(ei, attr);
    k_edge_expsum<<<grid_edges, TB>>>(ei, attr);
    k_edge_norm<<<grid_edges, TB>>>(ei, attr);

    // Output tuple element 0 = emb; acc starts at emb
    cudaMemcpyAsync(out, emb, node_bytes, cudaMemcpyDeviceToDevice);
    cudaMemcpyAsync(acc, emb, node_bytes, cudaMemcpyDeviceToDevice);

    // Layer 1: emb -> bufA
    cudaMemsetAsync(bufA, 0, node_bytes);
    k_propagate<<<grid_prop, TB>>>(emb, bufA, ei);
    k_accumulate<<<grid_nd, TB>>>(acc, bufA);

    // Layer 2: bufA -> bufB
    cudaMemsetAsync(bufB, 0, node_bytes);
    k_propagate<<<grid_prop, TB>>>(bufA, bufB, ei);
    k_accumulate<<<grid_nd, TB>>>(acc, bufB);

    // Layer 3: bufB -> bufA ; final mean over 4 snapshots
    cudaMemsetAsync(bufA, 0, node_bytes);
    k_propagate<<<grid_prop, TB>>>(bufB, bufA, ei);
    k_accumulate_scale<<<grid_nd, TB>>>(acc, bufA, 0.25f);
}

// round 2
// speedup vs baseline: 1.5517x; 1.5517x over previous
#include <cuda_runtime.h>
#include <cstdint>

// Problem constants (fixed by the dataset)
#define N_NODES 100000
#define N_EDGES 3200000
#define DIM     64
#define EPS     1e-16f

#define SCAN_T  1024
#define SCAN_C  98          // 1024 * 98 = 100352 >= N_NODES

// ---------------- device scratch (static globals: allocation-free) ----------
__device__ float g_in_sum[N_NODES];        // sum exp(l) over incoming edges (by to_)
__device__ float g_out_sum[N_NODES];       // sum exp(l) over outgoing edges (by from_)
__device__ int   g_deg[N_NODES];           // in-degree histogram (by to_)
__device__ int   g_rowptr[N_NODES + 1];    // CSR row pointers (by destination)
__device__ int   g_cursor[N_NODES];        // scatter cursors (init = rowptr)
__device__ int2  g_csr[N_EDGES];           // {src_node, norm_bits} per edge, grouped by dst
__device__ float g_bufA[(size_t)N_NODES * DIM];
__device__ float g_bufB[(size_t)N_NODES * DIM];

// ---------------- kernels ----------------------------------------------------

// One pass over edges: accumulate exp-sums for both softmaxes + in-degree histogram.
// Max-subtraction is dropped: logits ~ N(0,1) so exp() cannot overflow, and the
// only difference vs the reference is the 1e-16 eps scaling (~1e-14 relative).
__global__ void k_edge_sum(const int* __restrict__ ei, const float* __restrict__ attr) {
    int e = blockIdx.x * blockDim.x + threadIdx.x;
    if (e >= N_EDGES) return;
    int f = ei[e];
    int t = ei[e + N_EDGES];
    float el = __expf(attr[e]);     // s_temp = 1.0
    atomicAdd(&g_in_sum[t],  el);
    atomicAdd(&g_out_sum[f], el);
    atomicAdd(&g_deg[t], 1);
}

// Single-block exclusive scan of g_deg into g_rowptr (and g_cursor copy).
__global__ void k_scan() {
    __shared__ int sh[SCAN_T];
    int t = threadIdx.x;
    int base = t * SCAN_C;
    int local = 0;
    #pragma unroll 4
    for (int i = 0; i < SCAN_C; i++) {
        int idx = base + i;
        if (idx < N_NODES) local += g_deg[idx];
    }
    sh[t] = local;
    __syncthreads();
    // Hillis-Steele inclusive scan
    for (int off = 1; off < SCAN_T; off <<= 1) {
        int u = (t >= off) ? sh[t - off] : 0;
        __syncthreads();
        sh[t] += u;
        __syncthreads();
    }
    int run = sh[t] - local;   // exclusive prefix for this thread's chunk
    for (int i = 0; i < SCAN_C; i++) {
        int idx = base + i;
        if (idx < N_NODES) {
            g_rowptr[idx] = run;
            g_cursor[idx] = run;
            run += g_deg[idx];
        }
    }
    if (t == SCAN_T - 1) g_rowptr[N_NODES] = sh[SCAN_T - 1];
}

// Scatter edges into CSR (grouped by destination), computing norm inline:
// norm = exp(l) * rsqrt((s_in+eps)*(s_out+eps))
__global__ void k_scatter(const int* __restrict__ ei, const float* __restrict__ attr) {
    int e = blockIdx.x * blockDim.x + threadIdx.x;
    if (e >= N_EDGES) return;
    int f = ei[e];
    int t = ei[e + N_EDGES];
    float el = __expf(attr[e]);
    float w = el * rsqrtf((g_in_sum[t] + EPS) * (g_out_sum[f] + EPS));
    int pos = atomicAdd(&g_cursor[t], 1);
    g_csr[pos] = make_int2(f, __float_as_int(w));
}

// One warp per destination node. Gathers source rows (float2/lane = 256B/edge,
// coalesced), accumulates in registers, writes once. MODE 0: write dst + acc +=;
// MODE 1 (final layer): acc = (acc + cur) * 0.25, no dst write.
template <int MODE>
__global__ void k_layer(const float* __restrict__ src, float* __restrict__ dst,
                        float* __restrict__ acc) {
    int warp = (blockIdx.x * blockDim.x + threadIdx.x) >> 5;
    int lane = threadIdx.x & 31;
    if (warp >= N_NODES) return;
    int start = g_rowptr[warp];
    int end   = g_rowptr[warp + 1];

    const float2* s2 = reinterpret_cast<const float2*>(src);
    float ax = 0.0f, ay = 0.0f;

    for (int base = start; base < end; base += 32) {
        int k = base + lane;
        int2 ew = (k < end) ? g_csr[k] : make_int2(0, 0);
        int n = min(32, end - base);
        #pragma unroll 4
        for (int i = 0; i < n; i++) {
            int   s = __shfl_sync(0xFFFFFFFFu, ew.x, i);
            float w = __int_as_float(__shfl_sync(0xFFFFFFFFu, ew.y, i));
            float2 v = s2[(size_t)s * 32 + lane];
            ax = fmaf(w, v.x, ax);
            ay = fmaf(w, v.y, ay);
        }
    }

    size_t o = (size_t)warp * 32 + lane;
    float2* acc2 = reinterpret_cast<float2*>(acc);
    float2 av = acc2[o];
    if (MODE == 0) {
        reinterpret_cast<float2*>(dst)[o] = make_float2(ax, ay);
        acc2[o] = make_float2(av.x + ax, av.y + ay);
    } else {
        acc2[o] = make_float2((av.x + ax) * 0.25f, (av.y + ay) * 0.25f);
    }
}

// ---------------- launch ------------------------------------------------------
extern "C" void kernel_launch(void* const* d_in, const int* in_sizes, int n_in,
                              void* d_out, int out_size) {
    const float* emb  = (const float*)d_in[0];   // [N_NODES, 64]
    const int*   ei   = (const int*)d_in[1];     // [2, N_EDGES]
    const float* attr = (const float*)d_in[2];   // [N_EDGES]
    float* out = (float*)d_out;                  // [2 * N_NODES * 64]
    float* acc = out + (size_t)N_NODES * DIM;    // second tuple element

    float *bufA, *bufB, *inSum, *outSum;
    int *deg;
    cudaGetSymbolAddress((void**)&bufA,   g_bufA);
    cudaGetSymbolAddress((void**)&bufB,   g_bufB);
    cudaGetSymbolAddress((void**)&inSum,  g_in_sum);
    cudaGetSymbolAddress((void**)&outSum, g_out_sum);
    cudaGetSymbolAddress((void**)&deg,    g_deg);

    const size_t node_bytes = (size_t)N_NODES * DIM * sizeof(float);
    const int TB = 256;
    const int grid_edges = (N_EDGES + TB - 1) / TB;
    const int grid_layer = (N_NODES * 32 + 1024 - 1) / 1024;   // warp per node, 1024-thread blocks

    // Zero stats
    cudaMemsetAsync(inSum,  0, N_NODES * sizeof(float));
    cudaMemsetAsync(outSum, 0, N_NODES * sizeof(float));
    cudaMemsetAsync(deg,    0, N_NODES * sizeof(int));

    // Softmax denominators + degree histogram (one edge pass)
    k_edge_sum<<<grid_edges, TB>>>(ei, attr);
    // CSR row pointers
    k_scan<<<1, SCAN_T>>>();
    // CSR scatter with inline norm computation
    k_scatter<<<grid_edges, TB>>>(ei, attr);

    // Output tuple element 0 = emb; acc starts at emb
    cudaMemcpyAsync(out, emb, node_bytes, cudaMemcpyDeviceToDevice);
    cudaMemcpyAsync(acc, emb, node_bytes, cudaMemcpyDeviceToDevice);

    // 3 propagation layers (gather formulation, no atomics)
    k_layer<0><<<grid_layer, 1024>>>(emb,  bufA, acc);
    k_layer<0><<<grid_layer, 1024>>>(bufA, bufB, acc);
    k_layer<1><<<grid_layer, 1024>>>(bufB, bufA, acc);   // dst unused in MODE 1
}

// round 3
// speedup vs baseline: 1.6120x; 1.0388x over previous
#include <cuda_runtime.h>
#include <cstdint>

// Problem constants (fixed by the dataset)
#define N_NODES 100000
#define N_EDGES 3200000
#define DIM     64
#define EPS     1e-16f

#define SCAN_T  1024
#define SCAN_C  98          // 1024 * 98 = 100352 >= N_NODES

// ---------------- device scratch (static globals: allocation-free) ----------
__device__ float g_in_sum[N_NODES];        // sum exp(l) over incoming edges (by to_)
__device__ float g_out_sum[N_NODES];       // sum exp(l) over outgoing edges (by from_)
__device__ int   g_deg[N_NODES];           // in-degree histogram (by to_)
__device__ int   g_rank[N_EDGES];          // per-edge rank within its destination
__device__ int   g_rowptr[N_NODES + 1];    // CSR row pointers (by destination)
__device__ int2  g_csr[N_EDGES];           // {src_node, norm_bits} per edge, grouped by dst
__device__ float g_bufA[(size_t)N_NODES * DIM];
__device__ float g_bufB[(size_t)N_NODES * DIM];

// ---------------- kernels ----------------------------------------------------

// One pass over edges: exp-sums for both softmaxes + in-degree histogram,
// recording each edge's rank within its destination (atomic-free scatter later).
// Max-subtraction dropped: logits ~ N(0,1), exp() cannot overflow; only
// difference vs reference is the 1e-16 eps scaling (~1e-14 relative).
__global__ void k_edge_sum(const int* __restrict__ ei, const float* __restrict__ attr) {
    int e = blockIdx.x * blockDim.x + threadIdx.x;
    if (e >= N_EDGES) return;
    int f = ei[e];
    int t = ei[e + N_EDGES];
    float el = __expf(attr[e]);     // s_temp = 1.0
    atomicAdd(&g_in_sum[t],  el);
    atomicAdd(&g_out_sum[f], el);
    g_rank[e] = atomicAdd(&g_deg[t], 1);
}

// Single-block exclusive scan of g_deg into g_rowptr.
__global__ void k_scan() {
    __shared__ int sh[SCAN_T];
    int t = threadIdx.x;
    int base = t * SCAN_C;
    int local = 0;
    #pragma unroll 4
    for (int i = 0; i < SCAN_C; i++) {
        int idx = base + i;
        if (idx < N_NODES) local += g_deg[idx];
    }
    sh[t] = local;
    __syncthreads();
    for (int off = 1; off < SCAN_T; off <<= 1) {
        int u = (t >= off) ? sh[t - off] : 0;
        __syncthreads();
        sh[t] += u;
        __syncthreads();
    }
    int run = sh[t] - local;   // exclusive prefix for this thread's chunk
    for (int i = 0; i < SCAN_C; i++) {
        int idx = base + i;
        if (idx < N_NODES) {
            g_rowptr[idx] = run;
            run += g_deg[idx];
        }
    }
    if (t == SCAN_T - 1) g_rowptr[N_NODES] = sh[SCAN_T - 1];
}

// Scatter edges into CSR (grouped by destination), norm computed inline.
// Atomic-free: position = rowptr[t] + rank[e].
__global__ void k_scatter(const int* __restrict__ ei, const float* __restrict__ attr) {
    int e = blockIdx.x * blockDim.x + threadIdx.x;
    if (e >= N_EDGES) return;
    int f = ei[e];
    int t = ei[e + N_EDGES];
    float el = __expf(attr[e]);
    float w = el * rsqrtf((g_in_sum[t] + EPS) * (g_out_sum[f] + EPS));
    int pos = g_rowptr[t] + g_rank[e];
    g_csr[pos] = make_int2(f, __float_as_int(w));
}

// One warp per destination node. Half-warps each process one edge of a pair:
// per lane per 2 edges = 2 SHFL + 1 LDG.128 + 4 FMA. Cross-half reduce at end.
// MODE 2 (layer 1): dst = l1 ; acc = emb_row + l1   (src == emb)
// MODE 0 (middle) : dst = lk ; acc += lk
// MODE 1 (final)  : acc = (acc + lk) * 0.25, dst unused
template <int MODE>
__global__ void k_layer(const float* __restrict__ src, float* __restrict__ dst,
                        float* __restrict__ acc) {
    int warp = (blockIdx.x * blockDim.x + threadIdx.x) >> 5;
    int lane = threadIdx.x & 31;
    if (warp >= N_NODES) return;
    int start = g_rowptr[warp];
    int end   = g_rowptr[warp + 1];

    const float4* s4 = reinterpret_cast<const float4*>(src);
    int sub  = lane & 15;    // float4 slot within the 64-dim row
    int half = lane >> 4;    // which edge of the pair

    float4 a = make_float4(0.f, 0.f, 0.f, 0.f);

    for (int base = start; base < end; base += 32) {
        int k = base + lane;
        // out-of-range lanes carry {src=0, w=0}: contributes exactly 0
        int2 ew = (k < end) ? g_csr[k] : make_int2(0, 0);
        int c = min(32, end - base);
        if (c == 32) {
            #pragma unroll
            for (int i = 0; i < 16; i++) {
                int   srcLane = 2 * i + half;
                int   s = __shfl_sync(0xFFFFFFFFu, ew.x, srcLane);
                float w = __int_as_float(__shfl_sync(0xFFFFFFFFu, ew.y, srcLane));
                float4 v = s4[(size_t)s * 16 + sub];
                a.x = fmaf(w, v.x, a.x);
                a.y = fmaf(w, v.y, a.y);
                a.z = fmaf(w, v.z, a.z);
                a.w = fmaf(w, v.w, a.w);
            }
        } else {
            int nIter = (c + 1) >> 1;
            for (int i = 0; i < nIter; i++) {
                int   srcLane = 2 * i + half;          // <= 31 always
                int   s = __shfl_sync(0xFFFFFFFFu, ew.x, srcLane);
                float w = __int_as_float(__shfl_sync(0xFFFFFFFFu, ew.y, srcLane));
                float4 v = s4[(size_t)s * 16 + sub];
                a.x = fmaf(w, v.x, a.x);
                a.y = fmaf(w, v.y, a.y);
                a.z = fmaf(w, v.z, a.z);
                a.w = fmaf(w, v.w, a.w);
            }
        }
    }

    // combine the two half-warp accumulators
    a.x += __shfl_xor_sync(0xFFFFFFFFu, a.x, 16);
    a.y += __shfl_xor_sync(0xFFFFFFFFu, a.y, 16);
    a.z += __shfl_xor_sync(0xFFFFFFFFu, a.z, 16);
    a.w += __shfl_xor_sync(0xFFFFFFFFu, a.w, 16);

    if (lane < 16) {
        size_t o4 = (size_t)warp * 16 + sub;
        float4* acc4 = reinterpret_cast<float4*>(acc);
        if (MODE == 2) {
            reinterpret_cast<float4*>(dst)[o4] = a;
            float4 e0 = s4[o4];                 // src == emb for layer 1
            acc4[o4] = make_float4(e0.x + a.x, e0.y + a.y, e0.z + a.z, e0.w + a.w);
        } else if (MODE == 0) {
            reinterpret_cast<float4*>(dst)[o4] = a;
            float4 av = acc4[o4];
            acc4[o4] = make_float4(av.x + a.x, av.y + a.y, av.z + a.z, av.w + a.w);
        } else {
            float4 av = acc4[o4];
            acc4[o4] = make_float4((av.x + a.x) * 0.25f, (av.y + a.y) * 0.25f,
                                   (av.z + a.z) * 0.25f, (av.w + a.w) * 0.25f);
        }
    }
}

// ---------------- launch ------------------------------------------------------
extern "C" void kernel_launch(void* const* d_in, const int* in_sizes, int n_in,
                              void* d_out, int out_size) {
    const float* emb  = (const float*)d_in[0];   // [N_NODES, 64]
    const int*   ei   = (const int*)d_in[1];     // [2, N_EDGES]
    const float* attr = (const float*)d_in[2];   // [N_EDGES]
    float* out = (float*)d_out;                  // [2 * N_NODES * 64]
    float* acc = out + (size_t)N_NODES * DIM;    // second tuple element

    float *bufA, *bufB, *inSum, *outSum;
    int *deg;
    cudaGetSymbolAddress((void**)&bufA,   g_bufA);
    cudaGetSymbolAddress((void**)&bufB,   g_bufB);
    cudaGetSymbolAddress((void**)&inSum,  g_in_sum);
    cudaGetSymbolAddress((void**)&outSum, g_out_sum);
    cudaGetSymbolAddress((void**)&deg,    g_deg);

    const size_t node_bytes = (size_t)N_NODES * DIM * sizeof(float);
    const int TB = 256;
    const int grid_edges = (N_EDGES + TB - 1) / TB;
    const int grid_layer = (N_NODES * 32 + 1024 - 1) / 1024;   // warp per node

    // Zero stats
    cudaMemsetAsync(inSum,  0, N_NODES * sizeof(float));
    cudaMemsetAsync(outSum, 0, N_NODES * sizeof(float));
    cudaMemsetAsync(deg,    0, N_NODES * sizeof(int));

    // Softmax denominators + degree histogram + per-edge ranks
    k_edge_sum<<<grid_edges, TB>>>(ei, attr);
    // CSR row pointers
    k_scan<<<1, SCAN_T>>>();
    // CSR scatter (atomic-free) with inline norm computation
    k_scatter<<<grid_edges, TB>>>(ei, attr);

    // Output tuple element 0 = emb
    cudaMemcpyAsync(out, emb, node_bytes, cudaMemcpyDeviceToDevice);

    // 3 propagation layers (gather formulation, no atomics)
    k_layer<2><<<grid_layer, 1024>>>(emb,  bufA, acc);   // acc = emb + l1
    k_layer<0><<<grid_layer, 1024>>>(bufA, bufB, acc);   // acc += l2
    k_layer<1><<<grid_layer, 1024>>>(bufB, bufA, acc);   // acc = (acc + l3)/4
}

// round 4
// speedup vs baseline: 2.2360x; 1.3871x over previous
#include <cuda_runtime.h>
#include <cstdint>

// Problem constants (fixed by the dataset)
#define N_NODES 100000
#define N_EDGES 3200000
#define DIM     64
#define EPS     1e-16f

#define SB      98           // scan blocks: 98 * 1024 >= N_NODES

// ---------------- device scratch (static globals: allocation-free) ----------
__device__ float g_in_sum[N_NODES];        // sum exp(l) over incoming edges (by to_)
__device__ float g_out_sum[N_NODES];       // sum exp(l) over outgoing edges (by from_)
__device__ int   g_deg[N_NODES];           // in-degree histogram (by to_)
__device__ int   g_rank[N_EDGES];          // per-edge rank within its destination
__device__ int   g_rowptr[N_NODES + 1];    // CSR row pointers (by destination)
__device__ int   g_partial[SB];            // per-block degree sums
__device__ int   g_poff[SB];               // exclusive block offsets
__device__ int2  g_csr[N_EDGES];           // {src_node, norm_bits} grouped by dst
__device__ float g_bufA[(size_t)N_NODES * DIM];
__device__ float g_bufB[(size_t)N_NODES * DIM];

// ---------------- kernels ----------------------------------------------------

// One pass over edges: exp-sums for both softmaxes + in-degree histogram,
// recording each edge's rank within its destination (atomic-free scatter later).
// Max-subtraction dropped: logits ~ N(0,1), exp() cannot overflow; only
// difference vs reference is the 1e-16 eps scaling (~1e-14 relative).
__global__ void k_edge_sum(const int* __restrict__ ei, const float* __restrict__ attr) {
    int e = blockIdx.x * blockDim.x + threadIdx.x;
    if (e >= N_EDGES) return;
    int f = __ldg(&ei[e]);
    int t = __ldg(&ei[e + N_EDGES]);
    float el = __expf(__ldg(&attr[e]));     // s_temp = 1.0
    atomicAdd(&g_in_sum[t],  el);
    atomicAdd(&g_out_sum[f], el);
    g_rank[e] = atomicAdd(&g_deg[t], 1);
}

// --- 3-phase coalesced exclusive scan of g_deg -> g_rowptr -------------------
__global__ void k_scan_partial() {          // grid SB, block 1024
    __shared__ int sh[1024];
    int idx = blockIdx.x * 1024 + threadIdx.x;
    sh[threadIdx.x] = (idx < N_NODES) ? g_deg[idx] : 0;
    __syncthreads();
    for (int off = 512; off > 0; off >>= 1) {
        if (threadIdx.x < off) sh[threadIdx.x] += sh[threadIdx.x + off];
        __syncthreads();
    }
    if (threadIdx.x == 0) g_partial[blockIdx.x] = sh[0];
}

__global__ void k_scan_offsets() {          // 1 block, 1 thread (98 values)
    int run = 0;
    for (int i = 0; i < SB; i++) { g_poff[i] = run; run += g_partial[i]; }
    g_rowptr[N_NODES] = run;
}

__global__ void k_scan_final() {            // grid SB, block 1024
    __shared__ int sh[1024];
    int idx = blockIdx.x * 1024 + threadIdx.x;
    int v = (idx < N_NODES) ? g_deg[idx] : 0;
    sh[threadIdx.x] = v;
    __syncthreads();
    for (int off = 1; off < 1024; off <<= 1) {      // Hillis-Steele inclusive
        int u = (threadIdx.x >= off) ? sh[threadIdx.x - off] : 0;
        __syncthreads();
        sh[threadIdx.x] += u;
        __syncthreads();
    }
    if (idx < N_NODES) g_rowptr[idx] = g_poff[blockIdx.x] + sh[threadIdx.x] - v;
}

// Scatter edges into CSR (grouped by destination), norm computed inline.
// Atomic-free: position = rowptr[t] + rank[e].
__global__ void k_scatter(const int* __restrict__ ei, const float* __restrict__ attr) {
    int e = blockIdx.x * blockDim.x + threadIdx.x;
    if (e >= N_EDGES) return;
    int f = __ldg(&ei[e]);
    int t = __ldg(&ei[e + N_EDGES]);
    float el = __expf(__ldg(&attr[e]));
    float w = el * rsqrtf((g_in_sum[t] + EPS) * (g_out_sum[f] + EPS));
    int pos = g_rowptr[t] + g_rank[e];
    g_csr[pos] = make_int2(f, __float_as_int(w));
}

// One warp per destination node; float2 per lane covers the 64-dim row.
// CSR entries are read via uniform broadcast loads (all lanes, same address:
// 1 sector, L1-resident) -> per edge: 2 LDG + 2 FMA, no shfl dependency chain.
// MODE 2 (layer 1): dst = l1 ; acc = emb_row + l1   (src == emb)
// MODE 0 (middle) : dst = lk ; acc += lk
// MODE 1 (final)  : acc = (acc + lk) * 0.25, dst unused
template <int MODE>
__global__ void k_layer(const float* __restrict__ src, float* __restrict__ dst,
                        float* __restrict__ acc) {
    int warp = (blockIdx.x * blockDim.x + threadIdx.x) >> 5;
    int lane = threadIdx.x & 31;
    if (warp >= N_NODES) return;
    int start = g_rowptr[warp];
    int end   = g_rowptr[warp + 1];

    const float2* s2 = reinterpret_cast<const float2*>(src);
    float ax = 0.0f, ay = 0.0f;

    int k = start;
    // main unrolled-by-8 stretch: independent broadcast + gather loads
    for (; k + 8 <= end; k += 8) {
        #pragma unroll
        for (int i = 0; i < 8; i++) {
            int2 e = __ldg(&g_csr[k + i]);
            float w = __int_as_float(e.y);
            float2 v = __ldg(&s2[(size_t)e.x * 32 + lane]);
            ax = fmaf(w, v.x, ax);
            ay = fmaf(w, v.y, ay);
        }
    }
    for (; k < end; k++) {
        int2 e = __ldg(&g_csr[k]);
        float w = __int_as_float(e.y);
        float2 v = __ldg(&s2[(size_t)e.x * 32 + lane]);
        ax = fmaf(w, v.x, ax);
        ay = fmaf(w, v.y, ay);
    }

    size_t o = (size_t)warp * 32 + lane;
    float2* acc2 = reinterpret_cast<float2*>(acc);
    if (MODE == 2) {
        reinterpret_cast<float2*>(dst)[o] = make_float2(ax, ay);
        float2 e0 = s2[o];                  // src == emb for layer 1
        acc2[o] = make_float2(e0.x + ax, e0.y + ay);
    } else if (MODE == 0) {
        reinterpret_cast<float2*>(dst)[o] = make_float2(ax, ay);
        float2 av = acc2[o];
        acc2[o] = make_float2(av.x + ax, av.y + ay);
    } else {
        float2 av = acc2[o];
        acc2[o] = make_float2((av.x + ax) * 0.25f, (av.y + ay) * 0.25f);
    }
}

// ---------------- launch ------------------------------------------------------
extern "C" void kernel_launch(void* const* d_in, const int* in_sizes, int n_in,
                              void* d_out, int out_size) {
    const float* emb  = (const float*)d_in[0];   // [N_NODES, 64]
    const int*   ei   = (const int*)d_in[1];     // [2, N_EDGES]
    const float* attr = (const float*)d_in[2];   // [N_EDGES]
    float* out = (float*)d_out;                  // [2 * N_NODES * 64]
    float* acc = out + (size_t)N_NODES * DIM;    // second tuple element

    float *bufA, *bufB, *inSum, *outSum;
    int *deg;
    cudaGetSymbolAddress((void**)&bufA,   g_bufA);
    cudaGetSymbolAddress((void**)&bufB,   g_bufB);
    cudaGetSymbolAddress((void**)&inSum,  g_in_sum);
    cudaGetSymbolAddress((void**)&outSum, g_out_sum);
    cudaGetSymbolAddress((void**)&deg,    g_deg);

    const size_t node_bytes = (size_t)N_NODES * DIM * sizeof(float);
    const int TB = 256;
    const int grid_edges = (N_EDGES + TB - 1) / TB;
    const int grid_layer = (N_NODES * 32 + 511) / 512;   // warp per node, 512-thread blocks

    // Zero stats
    cudaMemsetAsync(inSum,  0, N_NODES * sizeof(float));
    cudaMemsetAsync(outSum, 0, N_NODES * sizeof(float));
    cudaMemsetAsync(deg,    0, N_NODES * sizeof(int));

    // Softmax denominators + degree histogram + per-edge ranks
    k_edge_sum<<<grid_edges, TB>>>(ei, attr);
    // CSR row pointers (coalesced 3-phase scan)
    k_scan_partial<<<SB, 1024>>>();
    k_scan_offsets<<<1, 1>>>();
    k_scan_final<<<SB, 1024>>>();
    // CSR scatter (atomic-free) with inline norm computation
    k_scatter<<<grid_edges, TB>>>(ei, attr);

    // Output tuple element 0 = emb
    cudaMemcpyAsync(out, emb, node_bytes, cudaMemcpyDeviceToDevice);

    // 3 propagation layers (gather formulation, no atomics)
    k_layer<2><<<grid_layer, 512>>>(emb,  bufA, acc);   // acc = emb + l1
    k_layer<0><<<grid_layer, 512>>>(bufA, bufB, acc);   // acc += l2
    k_layer<1><<<grid_layer, 512>>>(bufB, bufA, acc);   // acc = (acc + l3)/4
}

// round 5
// speedup vs baseline: 2.3365x; 1.0449x over previous
#include <cuda_runtime.h>
#include <cuda_fp16.h>
#include <cstdint>

// Problem constants (fixed by the dataset)
#define N_NODES 100000
#define N_EDGES 3200000
#define DIM     64
#define EPS     1e-16f

#define SB      98           // scan blocks: 98 * 1024 >= N_NODES

// ---------------- device scratch (static globals: allocation-free) ----------
__device__ float  g_in_sum[N_NODES];        // sum exp(l) over incoming edges (by to_)
__device__ float  g_out_sum[N_NODES];       // sum exp(l) over outgoing edges (by from_)
__device__ int    g_deg[N_NODES];           // in-degree histogram (by to_)
__device__ int    g_rank[N_EDGES];          // per-edge rank within its destination
__device__ int    g_rowptr[N_NODES + 1];    // CSR row pointers (by destination)
__device__ int    g_partial[SB];            // per-block degree sums
__device__ int    g_poff[SB];               // exclusive block offsets
__device__ int2   g_csr[N_EDGES];           // {src_node, norm_bits} grouped by dst
__device__ __half g_bufA[(size_t)N_NODES * DIM];   // fp16 intermediate node embs
__device__ __half g_bufB[(size_t)N_NODES * DIM];

// ---------------- kernels ----------------------------------------------------

// One pass over edges: exp-sums for both softmaxes + in-degree histogram,
// recording each edge's rank within its destination (atomic-free scatter later).
// Max-subtraction dropped: logits ~ N(0,1), exp() cannot overflow; only
// difference vs reference is the 1e-16 eps scaling (~1e-14 relative).
__global__ void k_edge_sum(const int* __restrict__ ei, const float* __restrict__ attr) {
    int e = blockIdx.x * blockDim.x + threadIdx.x;
    if (e >= N_EDGES) return;
    int f = __ldcs(&ei[e]);
    int t = __ldcs(&ei[e + N_EDGES]);
    float el = __expf(__ldcs(&attr[e]));    // s_temp = 1.0
    atomicAdd(&g_in_sum[t],  el);
    atomicAdd(&g_out_sum[f], el);
    g_rank[e] = atomicAdd(&g_deg[t], 1);
}

// --- 3-phase coalesced exclusive scan of g_deg -> g_rowptr -------------------
__global__ void k_scan_partial() {          // grid SB, block 1024
    __shared__ int sh[1024];
    int idx = blockIdx.x * 1024 + threadIdx.x;
    sh[threadIdx.x] = (idx < N_NODES) ? g_deg[idx] : 0;
    __syncthreads();
    for (int off = 512; off > 0; off >>= 1) {
        if (threadIdx.x < off) sh[threadIdx.x] += sh[threadIdx.x + off];
        __syncthreads();
    }
    if (threadIdx.x == 0) g_partial[blockIdx.x] = sh[0];
}

__global__ void k_scan_offsets() {          // 1 block, 1 thread (98 values)
    int run = 0;
    for (int i = 0; i < SB; i++) { g_poff[i] = run; run += g_partial[i]; }
    g_rowptr[N_NODES] = run;
}

__global__ void k_scan_final() {            // grid SB, block 1024
    __shared__ int sh[1024];
    int idx = blockIdx.x * 1024 + threadIdx.x;
    int v = (idx < N_NODES) ? g_deg[idx] : 0;
    sh[threadIdx.x] = v;
    __syncthreads();
    for (int off = 1; off < 1024; off <<= 1) {      // Hillis-Steele inclusive
        int u = (threadIdx.x >= off) ? sh[threadIdx.x - off] : 0;
        __syncthreads();
        sh[threadIdx.x] += u;
        __syncthreads();
    }
    if (idx < N_NODES) g_rowptr[idx] = g_poff[blockIdx.x] + sh[threadIdx.x] - v;
}

// Scatter edges into CSR (grouped by destination), norm computed inline.
// Atomic-free: position = rowptr[t] + rank[e].
__global__ void k_scatter(const int* __restrict__ ei, const float* __restrict__ attr) {
    int e = blockIdx.x * blockDim.x + threadIdx.x;
    if (e >= N_EDGES) return;
    int f = __ldcs(&ei[e]);
    int t = __ldcs(&ei[e + N_EDGES]);
    float el = __expf(__ldcs(&attr[e]));
    float w = el * rsqrtf((g_in_sum[t] + EPS) * (g_out_sum[f] + EPS));
    int pos = g_rowptr[t] + __ldcs(&g_rank[e]);
    g_csr[pos] = make_int2(f, __float_as_int(w));
}

// One warp per destination node. CSR entries read via uniform broadcast loads
// (all lanes same address: 1 sector, L1-resident). Accumulation in fp32;
// intermediate node buffers in fp16 (half2/lane) to halve gather bytes.
// MODE 2 (layer 1): src fp32 emb -> dst fp16 ; acc = emb_row + l1
// MODE 0 (middle) : src fp16    -> dst fp16 ; acc += l2
// MODE 1 (final)  : src fp16    -> no dst   ; acc = (acc + l3) * 0.25
template <int MODE>
__global__ void k_layer(const void* __restrict__ src, __half* __restrict__ dst,
                        float* __restrict__ acc) {
    int warp = (blockIdx.x * blockDim.x + threadIdx.x) >> 5;
    int lane = threadIdx.x & 31;
    if (warp >= N_NODES) return;
    int start = g_rowptr[warp];
    int end   = g_rowptr[warp + 1];

    float ax = 0.0f, ay = 0.0f;

    if (MODE == 2) {
        const float2* s2 = reinterpret_cast<const float2*>(src);
        int k = start;
        for (; k + 8 <= end; k += 8) {
            #pragma unroll
            for (int i = 0; i < 8; i++) {
                int2 e = __ldg(&g_csr[k + i]);
                float w = __int_as_float(e.y);
                float2 v = __ldg(&s2[(size_t)e.x * 32 + lane]);
                ax = fmaf(w, v.x, ax);
                ay = fmaf(w, v.y, ay);
            }
        }
        for (; k < end; k++) {
            int2 e = __ldg(&g_csr[k]);
            float w = __int_as_float(e.y);
            float2 v = __ldg(&s2[(size_t)e.x * 32 + lane]);
            ax = fmaf(w, v.x, ax);
            ay = fmaf(w, v.y, ay);
        }
    } else {
        const __half2* s2 = reinterpret_cast<const __half2*>(src);
        int k = start;
        for (; k + 8 <= end; k += 8) {
            #pragma unroll
            for (int i = 0; i < 8; i++) {
                int2 e = __ldg(&g_csr[k + i]);
                float w = __int_as_float(e.y);
                float2 v = __half22float2(__ldg(&s2[(size_t)e.x * 32 + lane]));
                ax = fmaf(w, v.x, ax);
                ay = fmaf(w, v.y, ay);
            }
        }
        for (; k < end; k++) {
            int2 e = __ldg(&g_csr[k]);
            float w = __int_as_float(e.y);
            float2 v = __half22float2(__ldg(&s2[(size_t)e.x * 32 + lane]));
            ax = fmaf(w, v.x, ax);
            ay = fmaf(w, v.y, ay);
        }
    }

    size_t o = (size_t)warp * 32 + lane;
    float2* acc2 = reinterpret_cast<float2*>(acc);
    if (MODE == 2) {
        reinterpret_cast<__half2*>(dst)[o] = __float22half2_rn(make_float2(ax, ay));
        float2 e0 = reinterpret_cast<const float2*>(src)[o];   // src == emb
        acc2[o] = make_float2(e0.x + ax, e0.y + ay);
    } else if (MODE == 0) {
        reinterpret_cast<__half2*>(dst)[o] = __float22half2_rn(make_float2(ax, ay));
        float2 av = acc2[o];
        acc2[o] = make_float2(av.x + ax, av.y + ay);
    } else {
        float2 av = acc2[o];
        acc2[o] = make_float2((av.x + ax) * 0.25f, (av.y + ay) * 0.25f);
    }
}

// ---------------- launch ------------------------------------------------------
extern "C" void kernel_launch(void* const* d_in, const int* in_sizes, int n_in,
                              void* d_out, int out_size) {
    const float* emb  = (const float*)d_in[0];   // [N_NODES, 64]
    const int*   ei   = (const int*)d_in[1];     // [2, N_EDGES]
    const float* attr = (const float*)d_in[2];   // [N_EDGES]
    float* out = (float*)d_out;                  // [2 * N_NODES * 64]
    float* acc = out + (size_t)N_NODES * DIM;    // second tuple element

    __half *bufA, *bufB;
    float *inSum, *outSum;
    int *deg;
    cudaGetSymbolAddress((void**)&bufA,   g_bufA);
    cudaGetSymbolAddress((void**)&bufB,   g_bufB);
    cudaGetSymbolAddress((void**)&inSum,  g_in_sum);
    cudaGetSymbolAddress((void**)&outSum, g_out_sum);
    cudaGetSymbolAddress((void**)&deg,    g_deg);

    const size_t node_bytes = (size_t)N_NODES * DIM * sizeof(float);
    const int TB = 256;
    const int grid_edges = (N_EDGES + TB - 1) / TB;
    const int grid_layer = (N_NODES * 32 + 511) / 512;   // warp per node

    // Zero stats
    cudaMemsetAsync(inSum,  0, N_NODES * sizeof(float));
    cudaMemsetAsync(outSum, 0, N_NODES * sizeof(float));
    cudaMemsetAsync(deg,    0, N_NODES * sizeof(int));

    // Softmax denominators + degree histogram + per-edge ranks
    k_edge_sum<<<grid_edges, TB>>>(ei, attr);
    // CSR row pointers (coalesced 3-phase scan)
    k_scan_partial<<<SB, 1024>>>();
    k_scan_offsets<<<1, 1>>>();
    k_scan_final<<<SB, 1024>>>();
    // CSR scatter (atomic-free) with inline norm computation
    k_scatter<<<grid_edges, TB>>>(ei, attr);

    // Output tuple element 0 = emb
    cudaMemcpyAsync(out, emb, node_bytes, cudaMemcpyDeviceToDevice);

    // 3 propagation layers (gather formulation, no atomics; fp16 intermediates)
    k_layer<2><<<grid_layer, 512>>>(emb,  bufA, acc);   // acc = emb + l1
    k_layer<0><<<grid_layer, 512>>>(bufA, bufB, acc);   // acc += l2
    k_layer<1><<<grid_layer, 512>>>(bufB, nullptr, acc);// acc = (acc + l3)/4
}

// round 6
// speedup vs baseline: 2.3495x; 1.0056x over previous
#include <cuda_runtime.h>
#include <cuda_fp16.h>
#include <cstdint>

// Problem constants (fixed by the dataset)
#define N_NODES 100000
#define N_EDGES 3200000
#define DIM     64
#define EPS     1e-16f

#define SB      98           // scan blocks: 98 * 1024 >= N_NODES

// ---------------- device scratch (static globals: allocation-free) ----------
__device__ float  g_in_sum[N_NODES];        // sum exp(l) over incoming edges (by to_)
__device__ float  g_out_sum[N_NODES];       // sum exp(l) over outgoing edges (by from_)
__device__ float  g_rin[N_NODES];           // rsqrt(in_sum + eps)  per node
__device__ float  g_rout[N_NODES];          // rsqrt(out_sum + eps) per node
__device__ int    g_deg[N_NODES];           // in-degree histogram (by to_)
__device__ int    g_rank[N_EDGES];          // per-edge rank within its destination
__device__ int    g_rowptr[N_NODES + 1];    // CSR row pointers (by destination)
__device__ int    g_partial[SB];            // per-block degree sums
__device__ int    g_poff[SB];               // exclusive block offsets
__device__ int2   g_csr[N_EDGES];           // {src_node, exp(l)_bits} grouped by dst
__device__ __half g_buf0[(size_t)N_NODES * DIM];   // fp16 prescaled emb (c_f * emb)
__device__ __half g_bufA[(size_t)N_NODES * DIM];   // fp16 intermediates (c_t * y)
__device__ __half g_bufB[(size_t)N_NODES * DIM];

// ---------------- kernels ----------------------------------------------------

// One pass over edges: exp-sums for both softmaxes + in-degree histogram,
// recording each edge's rank within its destination (atomic-free scatter later).
// Max-subtraction dropped: logits ~ N(0,1), exp() cannot overflow; only
// difference vs reference is the 1e-16 eps scaling (~1e-14 relative).
__global__ void k_edge_sum(const int* __restrict__ ei, const float* __restrict__ attr) {
    int e = blockIdx.x * blockDim.x + threadIdx.x;
    if (e >= N_EDGES) return;
    int f = __ldcs(&ei[e]);
    int t = __ldcs(&ei[e + N_EDGES]);
    float el = __expf(__ldcs(&attr[e]));    // s_temp = 1.0
    atomicAdd(&g_in_sum[t],  el);
    atomicAdd(&g_out_sum[f], el);
    g_rank[e] = atomicAdd(&g_deg[t], 1);
}

// Per-node reciprocal square roots of the softmax denominators.
__global__ void k_rcp() {
    int i = blockIdx.x * blockDim.x + threadIdx.x;
    if (i >= N_NODES) return;
    g_rin[i]  = rsqrtf(g_in_sum[i]  + EPS);
    g_rout[i] = rsqrtf(g_out_sum[i] + EPS);
}

// Prescale: out = emb (tuple element 0) and buf0 = fp16(c_f * emb) in one pass.
__global__ void k_prescale(const float* __restrict__ emb, float* __restrict__ out) {
    int o = blockIdx.x * blockDim.x + threadIdx.x;          // float2 index
    if (o >= N_NODES * 32) return;
    int n = o >> 5;
    float c = g_rout[n];                                    // broadcast within row
    float2 v = reinterpret_cast<const float2*>(emb)[o];
    reinterpret_cast<float2*>(out)[o] = v;
    reinterpret_cast<__half2*>(g_buf0)[o] =
        __float22half2_rn(make_float2(v.x * c, v.y * c));
}

// --- 3-phase coalesced exclusive scan of g_deg -> g_rowptr -------------------
__global__ void k_scan_partial() {          // grid SB, block 1024
    __shared__ int sh[1024];
    int idx = blockIdx.x * 1024 + threadIdx.x;
    sh[threadIdx.x] = (idx < N_NODES) ? g_deg[idx] : 0;
    __syncthreads();
    for (int off = 512; off > 0; off >>= 1) {
        if (threadIdx.x < off) sh[threadIdx.x] += sh[threadIdx.x + off];
        __syncthreads();
    }
    if (threadIdx.x == 0) g_partial[blockIdx.x] = sh[0];
}

__global__ void k_scan_offsets() {          // 1 block, 1 thread (98 values)
    int run = 0;
    for (int i = 0; i < SB; i++) { g_poff[i] = run; run += g_partial[i]; }
    g_rowptr[N_NODES] = run;
}

__global__ void k_scan_final() {            // grid SB, block 1024
    __shared__ int sh[1024];
    int idx = blockIdx.x * 1024 + threadIdx.x;
    int v = (idx < N_NODES) ? g_deg[idx] : 0;
    sh[threadIdx.x] = v;
    __syncthreads();
    for (int off = 1; off < 1024; off <<= 1) {      // Hillis-Steele inclusive
        int u = (threadIdx.x >= off) ? sh[threadIdx.x - off] : 0;
        __syncthreads();
        sh[threadIdx.x] += u;
        __syncthreads();
    }
    if (idx < N_NODES) g_rowptr[idx] = g_poff[blockIdx.x] + sh[threadIdx.x] - v;
}

// Scatter edges into CSR (grouped by destination). Weight stored = exp(l) only;
// the rsqrt factors are applied per-row (r_in at accumulate, r_out baked into
// the source embeddings). Atomic-free: position = rowptr[t] + rank[e].
__global__ void k_scatter(const int* __restrict__ ei, const float* __restrict__ attr) {
    int e = blockIdx.x * blockDim.x + threadIdx.x;
    if (e >= N_EDGES) return;
    int f = __ldcs(&ei[e]);
    int t = __ldcs(&ei[e + N_EDGES]);
    float el = __expf(__ldcs(&attr[e]));
    int pos = g_rowptr[t] + __ldcs(&g_rank[e]);
    g_csr[pos] = make_int2(f, __float_as_int(el));
}

// One warp per destination node; half2 per lane covers the 64-dim row.
// y_t = r_in[t] * sum_e exp(l_e) * x'_f   where x' carries the r_out factor.
// dst stores fp16(r_out[t] * y_t) for the next layer; acc keeps fp32 y_t.
// MODE 2 (layer 1): acc = emb_row + y
// MODE 0 (middle) : acc += y
// MODE 1 (final)  : acc = (acc + y) * 0.25, no dst
template <int MODE>
__global__ void k_layer(const __half2* __restrict__ src, __half2* __restrict__ dst,
                        float* __restrict__ acc, const float* __restrict__ emb) {
    int warp = (blockIdx.x * blockDim.x + threadIdx.x) >> 5;
    int lane = threadIdx.x & 31;
    if (warp >= N_NODES) return;
    int start = g_rowptr[warp];
    int end   = g_rowptr[warp + 1];

    float ax = 0.0f, ay = 0.0f;

    int k = start;
    for (; k + 8 <= end; k += 8) {
        #pragma unroll
        for (int i = 0; i < 8; i++) {
            int2 e = __ldg(&g_csr[k + i]);
            float w = __int_as_float(e.y);
            float2 v = __half22float2(__ldg(&src[(size_t)e.x * 32 + lane]));
            ax = fmaf(w, v.x, ax);
            ay = fmaf(w, v.y, ay);
        }
    }
    for (; k < end; k++) {
        int2 e = __ldg(&g_csr[k]);
        float w = __int_as_float(e.y);
        float2 v = __half22float2(__ldg(&src[(size_t)e.x * 32 + lane]));
        ax = fmaf(w, v.x, ax);
        ay = fmaf(w, v.y, ay);
    }

    float rin = g_rin[warp];           // broadcast
    ax *= rin; ay *= rin;              // y_t

    size_t o = (size_t)warp * 32 + lane;
    float2* acc2 = reinterpret_cast<float2*>(acc);
    if (MODE != 1) {
        float rout = g_rout[warp];
        dst[o] = __float22half2_rn(make_float2(ax * rout, ay * rout));
    }
    if (MODE == 2) {
        float2 e0 = reinterpret_cast<const float2*>(emb)[o];
        acc2[o] = make_float2(e0.x + ax, e0.y + ay);
    } else if (MODE == 0) {
        float2 av = acc2[o];
        acc2[o] = make_float2(av.x + ax, av.y + ay);
    } else {
        float2 av = acc2[o];
        acc2[o] = make_float2((av.x + ax) * 0.25f, (av.y + ay) * 0.25f);
    }
}

// ---------------- launch ------------------------------------------------------
extern "C" void kernel_launch(void* const* d_in, const int* in_sizes, int n_in,
                              void* d_out, int out_size) {
    const float* emb  = (const float*)d_in[0];   // [N_NODES, 64]
    const int*   ei   = (const int*)d_in[1];     // [2, N_EDGES]
    const float* attr = (const float*)d_in[2];   // [N_EDGES]
    float* out = (float*)d_out;                  // [2 * N_NODES * 64]
    float* acc = out + (size_t)N_NODES * DIM;    // second tuple element

    __half2 *buf0, *bufA, *bufB;
    float *inSum, *outSum;
    int *deg;
    cudaGetSymbolAddress((void**)&buf0,   g_buf0);
    cudaGetSymbolAddress((void**)&bufA,   g_bufA);
    cudaGetSymbolAddress((void**)&bufB,   g_bufB);
    cudaGetSymbolAddress((void**)&inSum,  g_in_sum);
    cudaGetSymbolAddress((void**)&outSum, g_out_sum);
    cudaGetSymbolAddress((void**)&deg,    g_deg);

    const int TB = 256;
    const int grid_edges = (N_EDGES + TB - 1) / TB;
    const int grid_nodes = (N_NODES + TB - 1) / TB;
    const int grid_pre   = (N_NODES * 32 + TB - 1) / TB;
    const int grid_layer = (N_NODES * 32 + 511) / 512;   // warp per node

    // Zero stats
    cudaMemsetAsync(inSum,  0, N_NODES * sizeof(float));
    cudaMemsetAsync(outSum, 0, N_NODES * sizeof(float));
    cudaMemsetAsync(deg,    0, N_NODES * sizeof(int));

    // Softmax denominators + degree histogram + per-edge ranks
    k_edge_sum<<<grid_edges, TB>>>(ei, attr);
    // Per-node rsqrt factors, then prescaled fp16 emb + out copy (fused)
    k_rcp<<<grid_nodes, TB>>>();
    k_prescale<<<grid_pre, TB>>>(emb, out);
    // CSR row pointers (coalesced 3-phase scan)
    k_scan_partial<<<SB, 1024>>>();
    k_scan_offsets<<<1, 1>>>();
    k_scan_final<<<SB, 1024>>>();
    // CSR scatter (atomic-free, no random stat reads)
    k_scatter<<<grid_edges, TB>>>(ei, attr);

    // 3 propagation layers (gather formulation, fp16 sources, fp32 accum)
    k_layer<2><<<grid_layer, 512>>>(buf0, bufA, acc, emb);   // acc = emb + l1
    k_layer<0><<<grid_layer, 512>>>(bufA, bufB, acc, emb);   // acc += l2
    k_layer<1><<<grid_layer, 512>>>(bufB, nullptr, acc, emb);// acc = (acc+l3)/4
}